// round 14
// baseline (speedup 1.0000x reference)
#include <cuda_runtime.h>
#include <cuda_fp16.h>
#include <stdint.h>

#define NN    50000
#define HID   128
#define NREL  3
#define EMAX  800000

// ---------------- scratch (device globals; 16B-aligned) ----------------------
__device__ __align__(16) float  g_h  [(size_t)NN * HID];       // current features (fp32)
__device__ __align__(16) __half g_hw [NREL][(size_t)NN * HID]; // (h @ w[r]) * dis[r], fp16
__device__ __align__(16) int    g_deg[NREL][NN];
__device__ __align__(16) int    g_off[NREL][NN + 1];           // CSR row offsets
__device__ __align__(16) int    g_cur[NREL][NN];               // fill cursors
__device__ __align__(16) int    g_csr[NREL][EMAX];             // src sorted by dst

// ---------------- GEMM body: single smem buffer + register prefetch -----------
// MODE 0: g_h    = relu(A @ B + bias)          (embedder)
// MODE 1: g_hw[r]= fp16( (g_h @ B[r]) * rsqrt(deg+1) )  (relation GEMMs)
template <int BM, int BN, int BK, int TM, int TN, int MODE>
__device__ __forceinline__ void sgemm_body(const float* __restrict__ Aext,
                                           const float* __restrict__ Bmat,
                                           const float* __restrict__ bias,
                                           int M, int K, int r, int tilex) {
    const float* A = (MODE == 0) ? Aext : g_h;
    const float* B = Bmat + (size_t)r * K * BN;

    __shared__ __align__(16) float As[BK][BM + 4];   // transposed A tile
    __shared__ __align__(16) float Bs[BK][BN];

    const int tid  = threadIdx.x;
    constexpr int TC = BN / TN;
    const int trow = tid / TC;
    const int tcol = tid % TC;
    const int rowBase = tilex * BM;

    float acc[TM][TN];
#pragma unroll
    for (int i = 0; i < TM; i++)
#pragma unroll
        for (int j = 0; j < TN; j++) acc[i][j] = 0.f;

    constexpr int ACNT = BM * BK / 4;   // float4s per A tile
    constexpr int BCNT = BK * BN / 4;
    constexpr int AF4  = (ACNT + 255) / 256;
    constexpr int BF4  = (BCNT + 255) / 256;
    float4 va[AF4], vb[BF4];

    const int ntiles = K / BK;

    auto fetch = [&](int k0) {
#pragma unroll
        for (int v = 0; v < AF4; v++) {
            int g = tid + v * 256;
            if ((ACNT % 256 == 0) || g < ACNT) {
                int row = g / (BK / 4), c4 = g % (BK / 4);
                int gr = rowBase + row; if (gr >= M) gr = M - 1;
                va[v] = *(const float4*)&A[(size_t)gr * K + k0 + c4 * 4];
            }
        }
#pragma unroll
        for (int v = 0; v < BF4; v++) {
            int g = tid + v * 256;
            if ((BCNT % 256 == 0) || g < BCNT) {
                int row = g / (BN / 4), c4 = g % (BN / 4);
                vb[v] = *(const float4*)&B[(size_t)(k0 + row) * BN + c4 * 4];
            }
        }
    };
    auto commit = [&]() {
#pragma unroll
        for (int v = 0; v < AF4; v++) {
            int g = tid + v * 256;
            if ((ACNT % 256 == 0) || g < ACNT) {
                int row = g / (BK / 4), c4 = g % (BK / 4);
                As[c4 * 4 + 0][row] = va[v].x;
                As[c4 * 4 + 1][row] = va[v].y;
                As[c4 * 4 + 2][row] = va[v].z;
                As[c4 * 4 + 3][row] = va[v].w;
            }
        }
#pragma unroll
        for (int v = 0; v < BF4; v++) {
            int g = tid + v * 256;
            if ((BCNT % 256 == 0) || g < BCNT) {
                int row = g / (BN / 4), c4 = g % (BN / 4);
                *(float4*)&Bs[row][c4 * 4] = vb[v];
            }
        }
    };

    fetch(0);
    commit();
    __syncthreads();

    for (int t = 0; t < ntiles; t++) {
        if (t + 1 < ntiles) fetch((t + 1) * BK);
#pragma unroll
        for (int kk = 0; kk < BK; kk++) {
            float a[TM], b[TN];
#pragma unroll
            for (int i = 0; i < TM; i++) a[i] = As[kk][trow * TM + i];
#pragma unroll
            for (int j = 0; j < TN; j++) b[j] = Bs[kk][tcol * TN + j];
#pragma unroll
            for (int i = 0; i < TM; i++)
#pragma unroll
                for (int j = 0; j < TN; j++)
                    acc[i][j] = fmaf(a[i], b[j], acc[i][j]);
        }
        __syncthreads();
        if (t + 1 < ntiles) {
            commit();
            __syncthreads();
        }
    }

#pragma unroll
    for (int i = 0; i < TM; i++) {
        int gr = rowBase + trow * TM + i;
        if (gr >= M) continue;
        if (MODE == 1) {
            float dscale = rsqrtf((float)g_deg[r][gr] + 1.0f);
#pragma unroll
            for (int j = 0; j < TN; j += 2) {
                int gc = tcol * TN + j;
                __half2 hv = __floats2half2_rn(acc[i][j] * dscale,
                                               acc[i][j + 1] * dscale);
                *(__half2*)&g_hw[r][(size_t)gr * BN + gc] = hv;
            }
        } else {
#pragma unroll
            for (int j = 0; j < TN; j++) {
                int gc = tcol * TN + j;
                g_h[(size_t)gr * BN + gc] = fmaxf(acc[i][j] + bias[gc], 0.f);
            }
        }
    }
}

// ---------------- CSR-build device bodies --------------------------------------
__device__ void count_body(const int* __restrict__ ei, int E, int bid, int nb) {
#pragma unroll
    for (int r = 0; r < NREL; r++) {
        const int* dst = ei + (size_t)(2 * r + 1) * E;
        for (int e = bid * 256 + (int)threadIdx.x; e < E; e += nb * 256) {
            int d = dst[e];
            if ((unsigned)d < NN) atomicAdd(&g_deg[r][d], 1);
        }
    }
}

// int4-vectorized fill: 4 edges/iteration -> 4 independent atomic chains (MLP 4)
__device__ void fill_body(const int* __restrict__ ei, int E, int bid, int nb) {
    const int nthreads = nb * 256;
    const int gtid = bid * 256 + (int)threadIdx.x;
    const int E4 = E >> 2;   // E = 800000, divisible by 4
#pragma unroll
    for (int r = 0; r < NREL; r++) {
        const int4* src4 = (const int4*)(ei + (size_t)(2 * r) * E);
        const int4* dst4 = (const int4*)(ei + (size_t)(2 * r + 1) * E);
        for (int i = gtid; i < E4; i += nthreads) {
            int4 s = src4[i];
            int4 d = dst4[i];
            int p0 = -1, p1 = -1, p2 = -1, p3 = -1;
            if ((unsigned)d.x < NN && (unsigned)s.x < NN) p0 = atomicAdd(&g_cur[r][d.x], 1);
            if ((unsigned)d.y < NN && (unsigned)s.y < NN) p1 = atomicAdd(&g_cur[r][d.y], 1);
            if ((unsigned)d.z < NN && (unsigned)s.z < NN) p2 = atomicAdd(&g_cur[r][d.z], 1);
            if ((unsigned)d.w < NN && (unsigned)s.w < NN) p3 = atomicAdd(&g_cur[r][d.w], 1);
            if (p0 >= 0) g_csr[r][p0] = s.x;
            if (p1 >= 0) g_csr[r][p1] = s.y;
            if (p2 >= 0) g_csr[r][p2] = s.z;
            if (p3 >= 0) g_csr[r][p3] = s.w;
        }
    }
}

// 256-thread block-sequential exclusive scan over one relation's degrees
__device__ void scan_body(int r) {
    __shared__ __align__(16) int wsum[8];
    __shared__ int carry;
    const int tid = threadIdx.x;
    const int lane = tid & 31;
    const int wid  = tid >> 5;
    if (tid == 0) carry = 0;
    __syncthreads();
    for (int base = 0; base < NN; base += 256) {
        int i = base + tid;
        int v = (i < NN) ? g_deg[r][i] : 0;
        int x = v;
#pragma unroll
        for (int o = 1; o < 32; o <<= 1) {
            int y = __shfl_up_sync(0xffffffffu, x, o);
            if (lane >= o) x += y;
        }
        if (lane == 31) wsum[wid] = x;
        __syncthreads();
        if (tid < 8) {
            int w = wsum[tid];
#pragma unroll
            for (int o = 1; o < 8; o <<= 1) {
                int y = __shfl_up_sync(0x000000ffu, w, o);
                if (tid >= o) w += y;
            }
            wsum[tid] = w;
        }
        __syncthreads();
        int excl = x - v + (wid > 0 ? wsum[wid - 1] : 0) + carry;
        if (i < NN) { g_off[r][i] = excl; g_cur[r][i] = excl; }
        int total = wsum[7];
        __syncthreads();
        if (tid == 0) carry += total;
        __syncthreads();
    }
    if (tid == 0) g_off[r][NN] = carry;
}

// ---------------- kernels -------------------------------------------------------
#define EMB_TILES 782   /* ceil(50000/64) */
#define REL_TILES 391   /* ceil(50000/128) */
#define CNT_BLKS  128
#define FILL_BLKS 592

__global__ void zero_deg_kernel() {
    int i = blockIdx.x * blockDim.x + threadIdx.x;
    if (i < NREL * NN) ((int*)g_deg)[i] = 0;
}

// K2: degree count (first 128 blocks — wave-1 start) + embedder GEMM
__global__ __launch_bounds__(256)
void k2_emb_count(const float* __restrict__ x, const float* __restrict__ emb_w,
                  const float* __restrict__ emb_b,
                  const int* __restrict__ ei, int E) {
    if (blockIdx.x < CNT_BLKS)
        count_body(ei, E, blockIdx.x, CNT_BLKS);
    else
        sgemm_body<64, 128, 20, 4, 8, 0>(x, emb_w, emb_b, NN, 300, 0,
                                         blockIdx.x - CNT_BLKS);
}

// K3: offset scan (first 3 blocks) + all three layer-0 relation GEMMs
__global__ __launch_bounds__(256)
void k3_rel_scan(const float* __restrict__ w) {
    int b = blockIdx.x;
    if (b < NREL) {
        scan_body(b);
    } else {
        b -= NREL;
        sgemm_body<128, 128, 16, 8, 8, 1>(nullptr, w, nullptr, NN, HID,
                                          b / REL_TILES, b % REL_TILES);
    }
}

// K4: CSR fill alone, full chip
__global__ __launch_bounds__(256)
void k4_fill(const int* __restrict__ ei, int E) {
    fill_body(ei, E, blockIdx.x, FILL_BLKS);
}

// layer-1 relation GEMMs (all 3)
__global__ __launch_bounds__(256)
void rel_gemm_kernel(const float* __restrict__ w) {
    sgemm_body<128, 128, 16, 8, 8, 1>(nullptr, w, nullptr, NN, HID,
                                      blockIdx.y, blockIdx.x);
}

// ---------------- CSR gather: warp per node, fp16 messages --------------------
// FUSE_FIN == 0: write relu(agg) to g_h (layer-0 epilogue)
// FUSE_FIN == 1: h = relu(agg), then out[node] = h @ lin_w + lin_b (final fused)
template <int FUSE_FIN>
__launch_bounds__(256)
__global__ void gather_kernel(const float* __restrict__ bias,
                              const float* __restrict__ lin_w,
                              const float* __restrict__ lin_b,
                              float* __restrict__ out) {
    __shared__ __align__(16) float sh[8][HID];   // per-warp h row (FUSE_FIN only)

    const int node = (blockIdx.x * blockDim.x + threadIdx.x) >> 5;
    const int lane = threadIdx.x & 31;
    const int warp = (threadIdx.x >> 5);
    if (node >= NN) return;
    const int c0 = lane * 4;

    float4 tot;
    tot.x = bias[c0 + 0] + bias[HID + c0 + 0] + bias[2 * HID + c0 + 0];
    tot.y = bias[c0 + 1] + bias[HID + c0 + 1] + bias[2 * HID + c0 + 1];
    tot.z = bias[c0 + 2] + bias[HID + c0 + 2] + bias[2 * HID + c0 + 2];
    tot.w = bias[c0 + 3] + bias[HID + c0 + 3] + bias[2 * HID + c0 + 3];

#pragma unroll
    for (int r = 0; r < NREL; r++) {
        const __half* hwr = g_hw[r];
        float4 a;
        {
            uint2 raw = *(const uint2*)&hwr[(size_t)node * HID + c0];
            float2 f01 = __half22float2(*(__half2*)&raw.x);
            float2 f23 = __half22float2(*(__half2*)&raw.y);
            a.x = f01.x; a.y = f01.y; a.z = f23.x; a.w = f23.y;
        }
        const int beg = g_off[r][node];
        const int end = g_off[r][node + 1];
        const int* __restrict__ csr = g_csr[r];
        for (int t = beg; t < end; t += 32) {
            int idx = (t + lane < end) ? csr[t + lane] : 0;
            int n = end - t; if (n > 32) n = 32;
            for (int j = 0; j < n; j++) {
                int s = __shfl_sync(0xffffffffu, idx, j);
                uint2 raw = *(const uint2*)&hwr[(size_t)s * HID + c0];
                float2 f01 = __half22float2(*(__half2*)&raw.x);
                float2 f23 = __half22float2(*(__half2*)&raw.y);
                a.x += f01.x; a.y += f01.y; a.z += f23.x; a.w += f23.y;
            }
        }
        float dd = rsqrtf((float)g_deg[r][node] + 1.0f);
        tot.x += a.x * dd; tot.y += a.y * dd;
        tot.z += a.z * dd; tot.w += a.w * dd;
    }
    tot.x = fmaxf(tot.x, 0.f);
    tot.y = fmaxf(tot.y, 0.f);
    tot.z = fmaxf(tot.z, 0.f);
    tot.w = fmaxf(tot.w, 0.f);

    if (FUSE_FIN == 0) {
        ((float4*)g_h)[(size_t)node * (HID / 4) + lane] = tot;
    } else {
        // stage h row in this warp's smem slice, then each lane computes 2 outputs
        *(float4*)&sh[warp][c0] = tot;
        __syncwarp();
        float acc0 = lin_b[2 * lane + 0];
        float acc1 = lin_b[2 * lane + 1];
#pragma unroll 4
        for (int c = 0; c < HID; c++) {
            float hc = sh[warp][c];                       // broadcast
            float2 wv = *(const float2*)&lin_w[c * 64 + 2 * lane];
            acc0 = fmaf(hc, wv.x, acc0);
            acc1 = fmaf(hc, wv.y, acc1);
        }
        *(float2*)&out[(size_t)node * 64 + 2 * lane] = make_float2(acc0, acc1);
    }
}

// ---------------- launch ------------------------------------------------------
extern "C" void kernel_launch(void* const* d_in, const int* in_sizes, int n_in,
                              void* d_out, int out_size) {
    const float* x     = (const float*)d_in[0];
    const int*   ei    = (const int*)d_in[1];   // int32 (JAX x64 disabled)
    const float* emb_w = (const float*)d_in[2];
    const float* emb_b = (const float*)d_in[3];
    const float* w0    = (const float*)d_in[4];
    const float* b0    = (const float*)d_in[5];
    const float* w1    = (const float*)d_in[6];
    const float* b1    = (const float*)d_in[7];
    const float* lin_w = (const float*)d_in[8];
    const float* lin_b = (const float*)d_in[9];
    float* out = (float*)d_out;

    const int E = in_sizes[1] / (2 * NREL);
    const int gather_blocks = (NN * 32 + 255) / 256;   // warp per node

    // stage 1: zero degree counters
    zero_deg_kernel<<<(NREL * NN + 255) / 256, 256>>>();

    // stage 2: degree count || embedder GEMM
    k2_emb_count<<<CNT_BLKS + EMB_TILES, 256>>>(x, emb_w, emb_b, ei, E);

    // stage 3: offset scan || layer-0 relation GEMMs (all 3 relations)
    k3_rel_scan<<<NREL + NREL * REL_TILES, 256>>>(w0);

    // stage 4: CSR fill (full chip, MLP-4)
    k4_fill<<<FILL_BLKS, 256>>>(ei, E);

    // layer-0 aggregate -> g_h
    gather_kernel<0><<<gather_blocks, 256>>>(b0, nullptr, nullptr, nullptr);

    // layer 1 relation GEMMs
    rel_gemm_kernel<<<dim3(REL_TILES, NREL), 256>>>(w1);

    // layer-1 aggregate fused with final linear -> out
    gather_kernel<1><<<gather_blocks, 256>>>(b1, lin_w, lin_b, out);
}

// round 15
// speedup vs baseline: 1.0328x; 1.0328x over previous
#include <cuda_runtime.h>
#include <cuda_fp16.h>
#include <stdint.h>

#define NN    50000
#define HID   128
#define NREL  3
#define EMAX  800000

// ---------------- scratch (device globals; 16B-aligned) ----------------------
__device__ __align__(16) float  g_h  [(size_t)NN * HID];       // current features (fp32)
__device__ __align__(16) __half g_hw [NREL][(size_t)NN * HID]; // (h @ w[r]) * dis[r], fp16
__device__ __align__(16) int    g_deg[NREL][NN];
__device__ __align__(16) int    g_off[NREL][NN + 1];           // CSR row offsets
__device__ __align__(16) int    g_cur[NREL][NN];               // fill cursors
__device__ __align__(16) int    g_csr[NREL][EMAX];             // src sorted by dst
__device__ int g_scan_done;                                    // scan completion flag

// ---------------- GEMM body: single smem buffer + register prefetch -----------
// MODE 0: g_h    = relu(A @ B + bias)          (embedder)
// MODE 1: g_hw[r]= fp16( (g_h @ B[r]) * rsqrt(deg+1) )  (relation GEMMs)
// MODE 2: Cext   = g_h @ B + bias              (final linear)
template <int BM, int BN, int BK, int TM, int TN, int MODE>
__device__ __forceinline__ void sgemm_body(const float* __restrict__ Aext,
                                           const float* __restrict__ Bmat,
                                           const float* __restrict__ bias,
                                           float* __restrict__ Cext,
                                           int M, int K, int r, int tilex) {
    const float* A = (MODE == 0) ? Aext : g_h;
    const float* B = Bmat + (size_t)r * K * BN;

    __shared__ __align__(16) float As[BK][BM + 4];   // transposed A tile
    __shared__ __align__(16) float Bs[BK][BN];

    const int tid  = threadIdx.x;
    constexpr int TC = BN / TN;
    const int trow = tid / TC;
    const int tcol = tid % TC;
    const int rowBase = tilex * BM;

    float acc[TM][TN];
#pragma unroll
    for (int i = 0; i < TM; i++)
#pragma unroll
        for (int j = 0; j < TN; j++) acc[i][j] = 0.f;

    constexpr int ACNT = BM * BK / 4;   // float4s per A tile
    constexpr int BCNT = BK * BN / 4;
    constexpr int AF4  = (ACNT + 255) / 256;
    constexpr int BF4  = (BCNT + 255) / 256;
    float4 va[AF4], vb[BF4];

    const int ntiles = K / BK;

    auto fetch = [&](int k0) {
#pragma unroll
        for (int v = 0; v < AF4; v++) {
            int g = tid + v * 256;
            if ((ACNT % 256 == 0) || g < ACNT) {
                int row = g / (BK / 4), c4 = g % (BK / 4);
                int gr = rowBase + row; if (gr >= M) gr = M - 1;
                va[v] = *(const float4*)&A[(size_t)gr * K + k0 + c4 * 4];
            }
        }
#pragma unroll
        for (int v = 0; v < BF4; v++) {
            int g = tid + v * 256;
            if ((BCNT % 256 == 0) || g < BCNT) {
                int row = g / (BN / 4), c4 = g % (BN / 4);
                vb[v] = *(const float4*)&B[(size_t)(k0 + row) * BN + c4 * 4];
            }
        }
    };
    auto commit = [&]() {
#pragma unroll
        for (int v = 0; v < AF4; v++) {
            int g = tid + v * 256;
            if ((ACNT % 256 == 0) || g < ACNT) {
                int row = g / (BK / 4), c4 = g % (BK / 4);
                As[c4 * 4 + 0][row] = va[v].x;
                As[c4 * 4 + 1][row] = va[v].y;
                As[c4 * 4 + 2][row] = va[v].z;
                As[c4 * 4 + 3][row] = va[v].w;
            }
        }
#pragma unroll
        for (int v = 0; v < BF4; v++) {
            int g = tid + v * 256;
            if ((BCNT % 256 == 0) || g < BCNT) {
                int row = g / (BN / 4), c4 = g % (BN / 4);
                *(float4*)&Bs[row][c4 * 4] = vb[v];
            }
        }
    };

    fetch(0);
    commit();
    __syncthreads();

    for (int t = 0; t < ntiles; t++) {
        if (t + 1 < ntiles) fetch((t + 1) * BK);
#pragma unroll
        for (int kk = 0; kk < BK; kk++) {
            float a[TM], b[TN];
#pragma unroll
            for (int i = 0; i < TM; i++) a[i] = As[kk][trow * TM + i];
#pragma unroll
            for (int j = 0; j < TN; j++) b[j] = Bs[kk][tcol * TN + j];
#pragma unroll
            for (int i = 0; i < TM; i++)
#pragma unroll
                for (int j = 0; j < TN; j++)
                    acc[i][j] = fmaf(a[i], b[j], acc[i][j]);
        }
        __syncthreads();
        if (t + 1 < ntiles) {
            commit();
            __syncthreads();
        }
    }

#pragma unroll
    for (int i = 0; i < TM; i++) {
        int gr = rowBase + trow * TM + i;
        if (gr >= M) continue;
        if (MODE == 1) {
            float dscale = rsqrtf((float)g_deg[r][gr] + 1.0f);
#pragma unroll
            for (int j = 0; j < TN; j += 2) {
                int gc = tcol * TN + j;
                __half2 hv = __floats2half2_rn(acc[i][j] * dscale,
                                               acc[i][j + 1] * dscale);
                *(__half2*)&g_hw[r][(size_t)gr * BN + gc] = hv;
            }
        } else {
#pragma unroll
            for (int j = 0; j < TN; j++) {
                int gc = tcol * TN + j;
                float v = acc[i][j];
                if (MODE == 0) {
                    g_h[(size_t)gr * BN + gc] = fmaxf(v + bias[gc], 0.f);
                } else {
                    Cext[(size_t)gr * BN + gc] = v + bias[gc];
                }
            }
        }
    }
}

// ---------------- CSR-build device bodies --------------------------------------
__device__ void count_body(const int* __restrict__ ei, int E, int bid, int nb) {
#pragma unroll
    for (int r = 0; r < NREL; r++) {
        const int* dst = ei + (size_t)(2 * r + 1) * E;
        for (int e = bid * 256 + (int)threadIdx.x; e < E; e += nb * 256) {
            int d = dst[e];
            if ((unsigned)d < NN) atomicAdd(&g_deg[r][d], 1);
        }
    }
}

// int4-vectorized fill: 4 edges/iteration
__device__ void fill_body(const int* __restrict__ ei, int E, int bid, int nb) {
    const int nthreads = nb * 256;
    const int gtid = bid * 256 + (int)threadIdx.x;
    const int E4 = E >> 2;   // E = 800000, divisible by 4
#pragma unroll
    for (int r = 0; r < NREL; r++) {
        const int4* src4 = (const int4*)(ei + (size_t)(2 * r) * E);
        const int4* dst4 = (const int4*)(ei + (size_t)(2 * r + 1) * E);
        for (int i = gtid; i < E4; i += nthreads) {
            int4 s = src4[i];
            int4 d = dst4[i];
            int p0 = -1, p1 = -1, p2 = -1, p3 = -1;
            if ((unsigned)d.x < NN && (unsigned)s.x < NN) p0 = atomicAdd(&g_cur[r][d.x], 1);
            if ((unsigned)d.y < NN && (unsigned)s.y < NN) p1 = atomicAdd(&g_cur[r][d.y], 1);
            if ((unsigned)d.z < NN && (unsigned)s.z < NN) p2 = atomicAdd(&g_cur[r][d.z], 1);
            if ((unsigned)d.w < NN && (unsigned)s.w < NN) p3 = atomicAdd(&g_cur[r][d.w], 1);
            if (p0 >= 0) g_csr[r][p0] = s.x;
            if (p1 >= 0) g_csr[r][p1] = s.y;
            if (p2 >= 0) g_csr[r][p2] = s.z;
            if (p3 >= 0) g_csr[r][p3] = s.w;
        }
    }
}

// 256-thread block-sequential exclusive scan over one relation's degrees
__device__ void scan_body(int r) {
    __shared__ __align__(16) int wsum[8];
    __shared__ int carry;
    const int tid = threadIdx.x;
    const int lane = tid & 31;
    const int wid  = tid >> 5;
    if (tid == 0) carry = 0;
    __syncthreads();
    for (int base = 0; base < NN; base += 256) {
        int i = base + tid;
        int v = (i < NN) ? g_deg[r][i] : 0;
        int x = v;
#pragma unroll
        for (int o = 1; o < 32; o <<= 1) {
            int y = __shfl_up_sync(0xffffffffu, x, o);
            if (lane >= o) x += y;
        }
        if (lane == 31) wsum[wid] = x;
        __syncthreads();
        if (tid < 8) {
            int w = wsum[tid];
#pragma unroll
            for (int o = 1; o < 8; o <<= 1) {
                int y = __shfl_up_sync(0x000000ffu, w, o);
                if (tid >= o) w += y;
            }
            wsum[tid] = w;
        }
        __syncthreads();
        int excl = x - v + (wid > 0 ? wsum[wid - 1] : 0) + carry;
        if (i < NN) { g_off[r][i] = excl; g_cur[r][i] = excl; }
        int total = wsum[7];
        __syncthreads();
        if (tid == 0) carry += total;
        __syncthreads();
    }
    if (tid == 0) {
        g_off[r][NN] = carry;
        __threadfence();                 // publish g_cur/g_off before flagging
        atomicAdd(&g_scan_done, 1);
    }
}

// ---------------- kernels -------------------------------------------------------
#define EMB_TILES 782   /* ceil(50000/64) */
#define REL_TILES 391   /* ceil(50000/128) */
#define CNT_BLKS  128
#define FILL_BLKS 592
#define K3_GEMM   (NREL * REL_TILES)    /* 1173 */

__global__ void zero_deg_kernel() {
    int i = blockIdx.x * blockDim.x + threadIdx.x;
    if (i == 0) g_scan_done = 0;
    if (i < NREL * NN) ((int*)g_deg)[i] = 0;
}

// K2: degree count (first 128 blocks — wave-1 start) + embedder GEMM
__global__ __launch_bounds__(256)
void k2_emb_count(const float* __restrict__ x, const float* __restrict__ emb_w,
                  const float* __restrict__ emb_b,
                  const int* __restrict__ ei, int E) {
    if (blockIdx.x < CNT_BLKS)
        count_body(ei, E, blockIdx.x, CNT_BLKS);
    else
        sgemm_body<64, 128, 20, 4, 8, 0>(x, emb_w, emb_b, nullptr, NN, 300, 0,
                                         blockIdx.x - CNT_BLKS);
}

// K3: scan (blocks 0-2, wave 1) + all layer-0 relation GEMMs + CSR fill
// (last 592 blocks; dispatched after ~wave 4, gated on scan flag so the
// fill's latency-bound work overlaps the GEMM tail instead of serializing).
__global__ __launch_bounds__(256)
void k3_rel_scan_fill(const float* __restrict__ w,
                      const int* __restrict__ ei, int E) {
    int b = blockIdx.x;
    if (b < NREL) {
        scan_body(b);
    } else if (b < NREL + K3_GEMM) {
        b -= NREL;
        sgemm_body<128, 128, 16, 8, 8, 1>(nullptr, w, nullptr, nullptr, NN, HID,
                                          b / REL_TILES, b % REL_TILES);
    } else {
        // wait until all 3 scans published their cursors (normally instant)
        if (threadIdx.x == 0)
            while (atomicAdd(&g_scan_done, 0) < NREL) { }
        __syncthreads();
        fill_body(ei, E, b - NREL - K3_GEMM, FILL_BLKS);
    }
}

// layer-1 relation GEMMs (all 3)
__global__ __launch_bounds__(256)
void rel_gemm_kernel(const float* __restrict__ w) {
    sgemm_body<128, 128, 16, 8, 8, 1>(nullptr, w, nullptr, nullptr, NN, HID,
                                      blockIdx.y, blockIdx.x);
}

// final linear
__global__ __launch_bounds__(256)
void fin_gemm_kernel(const float* __restrict__ w, const float* __restrict__ b,
                     float* __restrict__ out) {
    sgemm_body<128, 64, 16, 8, 4, 2>(nullptr, w, b, out, NN, HID, 0, blockIdx.x);
}

// ---------------- CSR gather: warp per node, fp16 messages, fused epilogue ----
__launch_bounds__(256)
__global__ void gather_kernel(const float* __restrict__ bias) {
    const int node = (blockIdx.x * blockDim.x + threadIdx.x) >> 5;
    const int lane = threadIdx.x & 31;
    if (node >= NN) return;
    const int c0 = lane * 4;

    float4 tot;
    tot.x = bias[c0 + 0] + bias[HID + c0 + 0] + bias[2 * HID + c0 + 0];
    tot.y = bias[c0 + 1] + bias[HID + c0 + 1] + bias[2 * HID + c0 + 1];
    tot.z = bias[c0 + 2] + bias[HID + c0 + 2] + bias[2 * HID + c0 + 2];
    tot.w = bias[c0 + 3] + bias[HID + c0 + 3] + bias[2 * HID + c0 + 3];

#pragma unroll
    for (int r = 0; r < NREL; r++) {
        const __half* hwr = g_hw[r];
        float4 a;
        {
            uint2 raw = *(const uint2*)&hwr[(size_t)node * HID + c0];
            float2 f01 = __half22float2(*(__half2*)&raw.x);
            float2 f23 = __half22float2(*(__half2*)&raw.y);
            a.x = f01.x; a.y = f01.y; a.z = f23.x; a.w = f23.y;
        }
        const int beg = g_off[r][node];
        const int end = g_off[r][node + 1];
        const int* __restrict__ csr = g_csr[r];
        for (int t = beg; t < end; t += 32) {
            int idx = (t + lane < end) ? csr[t + lane] : 0;
            int n = end - t; if (n > 32) n = 32;
            for (int j = 0; j < n; j++) {
                int s = __shfl_sync(0xffffffffu, idx, j);
                uint2 raw = *(const uint2*)&hwr[(size_t)s * HID + c0];
                float2 f01 = __half22float2(*(__half2*)&raw.x);
                float2 f23 = __half22float2(*(__half2*)&raw.y);
                a.x += f01.x; a.y += f01.y; a.z += f23.x; a.w += f23.y;
            }
        }
        float dd = rsqrtf((float)g_deg[r][node] + 1.0f);
        tot.x += a.x * dd; tot.y += a.y * dd;
        tot.z += a.z * dd; tot.w += a.w * dd;
    }
    tot.x = fmaxf(tot.x, 0.f);
    tot.y = fmaxf(tot.y, 0.f);
    tot.z = fmaxf(tot.z, 0.f);
    tot.w = fmaxf(tot.w, 0.f);
    ((float4*)g_h)[(size_t)node * (HID / 4) + lane] = tot;
}

// ---------------- launch ------------------------------------------------------
extern "C" void kernel_launch(void* const* d_in, const int* in_sizes, int n_in,
                              void* d_out, int out_size) {
    const float* x     = (const float*)d_in[0];
    const int*   ei    = (const int*)d_in[1];   // int32 (JAX x64 disabled)
    const float* emb_w = (const float*)d_in[2];
    const float* emb_b = (const float*)d_in[3];
    const float* w0    = (const float*)d_in[4];
    const float* b0    = (const float*)d_in[5];
    const float* w1    = (const float*)d_in[6];
    const float* b1    = (const float*)d_in[7];
    const float* lin_w = (const float*)d_in[8];
    const float* lin_b = (const float*)d_in[9];
    float* out = (float*)d_out;

    const int E = in_sizes[1] / (2 * NREL);
    const int gather_blocks = (NN * 32 + 255) / 256;   // warp per node

    // stage 1: zero degree counters + scan flag
    zero_deg_kernel<<<(NREL * NN + 255) / 256, 256>>>();

    // stage 2: degree count || embedder GEMM
    k2_emb_count<<<CNT_BLKS + EMB_TILES, 256>>>(x, emb_w, emb_b, ei, E);

    // stage 3: scan || layer-0 relation GEMMs || CSR fill (flag-gated tail)
    k3_rel_scan_fill<<<NREL + K3_GEMM + FILL_BLKS, 256>>>(w0, ei, E);

    // layer-0 aggregate
    gather_kernel<<<gather_blocks, 256>>>(b0);

    // layer 1
    rel_gemm_kernel<<<dim3(REL_TILES, NREL), 256>>>(w1);
    gather_kernel<<<gather_blocks, 256>>>(b1);

    // final linear
    fin_gemm_kernel<<<REL_TILES, 256>>>(lin_w, lin_b, out);
}

// round 16
// speedup vs baseline: 1.1140x; 1.0785x over previous
#include <cuda_runtime.h>
#include <cuda_fp16.h>
#include <stdint.h>

#define NN    50000
#define HID   128
#define NREL  3
#define EMAX  800000

// ---------------- scratch (device globals; 16B-aligned) ----------------------
__device__ __align__(16) float  g_h  [(size_t)NN * HID];       // current features (fp32)
__device__ __align__(16) __half g_hw [NREL][(size_t)NN * HID]; // (h @ w[r]) * dis[r], fp16
__device__ __align__(16) int    g_deg[NREL][NN];
__device__ __align__(16) int    g_off[NREL][NN + 1];           // CSR row offsets
__device__ __align__(16) int    g_cur[NREL][NN];               // fill cursors
__device__ __align__(16) int    g_csr[NREL][EMAX];             // src sorted by dst
__device__ int g_scan_done;                                    // scan completion flag

// ---------------- fp32 GEMM body (embedder + final linear) --------------------
// MODE 0: g_h  = relu(A @ B + bias)
// MODE 2: Cext = g_h @ B + bias
template <int BM, int BN, int BK, int TM, int TN, int MODE>
__device__ __forceinline__ void sgemm_body(const float* __restrict__ Aext,
                                           const float* __restrict__ Bmat,
                                           const float* __restrict__ bias,
                                           float* __restrict__ Cext,
                                           int M, int K, int tilex) {
    const float* A = (MODE == 0) ? Aext : g_h;
    const float* B = Bmat;

    __shared__ __align__(16) float As[BK][BM + 4];
    __shared__ __align__(16) float Bs[BK][BN];

    const int tid  = threadIdx.x;
    constexpr int TC = BN / TN;
    const int trow = tid / TC;
    const int tcol = tid % TC;
    const int rowBase = tilex * BM;

    float acc[TM][TN];
#pragma unroll
    for (int i = 0; i < TM; i++)
#pragma unroll
        for (int j = 0; j < TN; j++) acc[i][j] = 0.f;

    constexpr int ACNT = BM * BK / 4;
    constexpr int BCNT = BK * BN / 4;
    constexpr int AF4  = (ACNT + 255) / 256;
    constexpr int BF4  = (BCNT + 255) / 256;
    float4 va[AF4], vb[BF4];

    const int ntiles = K / BK;

    auto fetch = [&](int k0) {
#pragma unroll
        for (int v = 0; v < AF4; v++) {
            int g = tid + v * 256;
            if ((ACNT % 256 == 0) || g < ACNT) {
                int row = g / (BK / 4), c4 = g % (BK / 4);
                int gr = rowBase + row; if (gr >= M) gr = M - 1;
                va[v] = *(const float4*)&A[(size_t)gr * K + k0 + c4 * 4];
            }
        }
#pragma unroll
        for (int v = 0; v < BF4; v++) {
            int g = tid + v * 256;
            if ((BCNT % 256 == 0) || g < BCNT) {
                int row = g / (BN / 4), c4 = g % (BN / 4);
                vb[v] = *(const float4*)&B[(size_t)(k0 + row) * BN + c4 * 4];
            }
        }
    };
    auto commit = [&]() {
#pragma unroll
        for (int v = 0; v < AF4; v++) {
            int g = tid + v * 256;
            if ((ACNT % 256 == 0) || g < ACNT) {
                int row = g / (BK / 4), c4 = g % (BK / 4);
                As[c4 * 4 + 0][row] = va[v].x;
                As[c4 * 4 + 1][row] = va[v].y;
                As[c4 * 4 + 2][row] = va[v].z;
                As[c4 * 4 + 3][row] = va[v].w;
            }
        }
#pragma unroll
        for (int v = 0; v < BF4; v++) {
            int g = tid + v * 256;
            if ((BCNT % 256 == 0) || g < BCNT) {
                int row = g / (BN / 4), c4 = g % (BN / 4);
                *(float4*)&Bs[row][c4 * 4] = vb[v];
            }
        }
    };

    fetch(0);
    commit();
    __syncthreads();

    for (int t = 0; t < ntiles; t++) {
        if (t + 1 < ntiles) fetch((t + 1) * BK);
#pragma unroll
        for (int kk = 0; kk < BK; kk++) {
            float a[TM], b[TN];
#pragma unroll
            for (int i = 0; i < TM; i++) a[i] = As[kk][trow * TM + i];
#pragma unroll
            for (int j = 0; j < TN; j++) b[j] = Bs[kk][tcol * TN + j];
#pragma unroll
            for (int i = 0; i < TM; i++)
#pragma unroll
                for (int j = 0; j < TN; j++)
                    acc[i][j] = fmaf(a[i], b[j], acc[i][j]);
        }
        __syncthreads();
        if (t + 1 < ntiles) {
            commit();
            __syncthreads();
        }
    }

#pragma unroll
    for (int i = 0; i < TM; i++) {
        int gr = rowBase + trow * TM + i;
        if (gr >= M) continue;
#pragma unroll
        for (int j = 0; j < TN; j++) {
            int gc = tcol * TN + j;
            float v = acc[i][j];
            if (MODE == 0) {
                g_h[(size_t)gr * BN + gc] = fmaxf(v + bias[gc], 0.f);
            } else {
                Cext[(size_t)gr * BN + gc] = v + bias[gc];
            }
        }
    }
}

// ---------------- half2 HFMA2 GEMM body (relation GEMMs) ----------------------
// g_hw[r] = fp16( (g_h @ B[r]) * rsqrt(deg+1) ).  BM=64, BN=128, BK=16,
// TM=4 rows x TN=8 cols (4 half2 col-pairs).  fp16 accum promoted to fp32
// at every BK-tile boundary (16 k-steps) to bound rounding.
__device__ __forceinline__ void hgemm_body(const float* __restrict__ Bmat,
                                           int r, int tilex) {
    constexpr int BM = 64, BN = 128, BK = 16;
    const float* B = Bmat + (size_t)r * HID * BN;

    __shared__ __align__(16) __half2 As[BK][BM + 4];   // splat {a,a} per element
    __shared__ __align__(16) __half2 Bs[BK][BN / 2];   // col pairs

    const int tid  = threadIdx.x;
    const int trow = tid / 16;          // 0..15 -> 4 rows each
    const int tcol = tid % 16;          // 0..15 -> 8 cols (4 pairs) each
    const int rowBase = tilex * BM;

    float acc[4][8];
#pragma unroll
    for (int i = 0; i < 4; i++)
#pragma unroll
        for (int j = 0; j < 8; j++) acc[i][j] = 0.f;

    float4 va, vb[2];
    auto fetch = [&](int k0) {
        {   // A tile: 64x16 floats = 256 float4, 1/thread
            int row = tid / 4, c4 = tid % 4;
            int gr = rowBase + row; if (gr >= NN) gr = NN - 1;
            va = *(const float4*)&g_h[(size_t)gr * HID + k0 + c4 * 4];
        }
#pragma unroll
        for (int v = 0; v < 2; v++) {   // B tile: 16x128 floats = 512 float4
            int g = tid + v * 256;
            int row = g / 32, c4 = g % 32;
            vb[v] = *(const float4*)&B[(size_t)(k0 + row) * BN + c4 * 4];
        }
    };
    auto commit = [&]() {
        {
            int row = tid / 4, c4 = tid % 4;
            As[c4 * 4 + 0][row] = __float2half2_rn(va.x);
            As[c4 * 4 + 1][row] = __float2half2_rn(va.y);
            As[c4 * 4 + 2][row] = __float2half2_rn(va.z);
            As[c4 * 4 + 3][row] = __float2half2_rn(va.w);
        }
#pragma unroll
        for (int v = 0; v < 2; v++) {
            int g = tid + v * 256;
            int row = g / 32, c4 = g % 32;
            Bs[row][c4 * 2 + 0] = __floats2half2_rn(vb[v].x, vb[v].y);
            Bs[row][c4 * 2 + 1] = __floats2half2_rn(vb[v].z, vb[v].w);
        }
    };

    fetch(0);
    commit();
    __syncthreads();

    const __half2 hz = __floats2half2_rn(0.f, 0.f);
    for (int t = 0; t < HID / BK; t++) {
        if (t + 1 < HID / BK) fetch((t + 1) * BK);
        __half2 hacc[4][4];
#pragma unroll
        for (int i = 0; i < 4; i++)
#pragma unroll
            for (int jp = 0; jp < 4; jp++) hacc[i][jp] = hz;
#pragma unroll
        for (int kk = 0; kk < BK; kk++) {
            __half2 asp[4], bp[4];
            *(uint4*)asp = *(const uint4*)&As[kk][trow * 4];
            *(uint4*)bp  = *(const uint4*)&Bs[kk][tcol * 4];
#pragma unroll
            for (int i = 0; i < 4; i++)
#pragma unroll
                for (int jp = 0; jp < 4; jp++)
                    hacc[i][jp] = __hfma2(asp[i], bp[jp], hacc[i][jp]);
        }
        // promote fp16 chunk sums into fp32 accumulators
#pragma unroll
        for (int i = 0; i < 4; i++)
#pragma unroll
            for (int jp = 0; jp < 4; jp++) {
                float2 f = __half22float2(hacc[i][jp]);
                acc[i][jp * 2 + 0] += f.x;
                acc[i][jp * 2 + 1] += f.y;
            }
        __syncthreads();
        if (t + 1 < HID / BK) {
            commit();
            __syncthreads();
        }
    }

#pragma unroll
    for (int i = 0; i < 4; i++) {
        int gr = rowBase + trow * 4 + i;
        if (gr >= NN) continue;
        float dscale = rsqrtf((float)g_deg[r][gr] + 1.0f);
#pragma unroll
        for (int jp = 0; jp < 4; jp++) {
            int gc = tcol * 8 + jp * 2;
            __half2 hv = __floats2half2_rn(acc[i][jp * 2] * dscale,
                                           acc[i][jp * 2 + 1] * dscale);
            *(__half2*)&g_hw[r][(size_t)gr * BN + gc] = hv;
        }
    }
}

// ---------------- CSR-build device bodies --------------------------------------
__device__ void count_body(const int* __restrict__ ei, int E, int bid, int nb) {
#pragma unroll
    for (int r = 0; r < NREL; r++) {
        const int* dst = ei + (size_t)(2 * r + 1) * E;
        for (int e = bid * 256 + (int)threadIdx.x; e < E; e += nb * 256) {
            int d = dst[e];
            if ((unsigned)d < NN) atomicAdd(&g_deg[r][d], 1);
        }
    }
}

__device__ void fill_body(const int* __restrict__ ei, int E, int bid, int nb) {
    const int nthreads = nb * 256;
    const int gtid = bid * 256 + (int)threadIdx.x;
    const int E4 = E >> 2;
#pragma unroll
    for (int r = 0; r < NREL; r++) {
        const int4* src4 = (const int4*)(ei + (size_t)(2 * r) * E);
        const int4* dst4 = (const int4*)(ei + (size_t)(2 * r + 1) * E);
        for (int i = gtid; i < E4; i += nthreads) {
            int4 s = src4[i];
            int4 d = dst4[i];
            int p0 = -1, p1 = -1, p2 = -1, p3 = -1;
            if ((unsigned)d.x < NN && (unsigned)s.x < NN) p0 = atomicAdd(&g_cur[r][d.x], 1);
            if ((unsigned)d.y < NN && (unsigned)s.y < NN) p1 = atomicAdd(&g_cur[r][d.y], 1);
            if ((unsigned)d.z < NN && (unsigned)s.z < NN) p2 = atomicAdd(&g_cur[r][d.z], 1);
            if ((unsigned)d.w < NN && (unsigned)s.w < NN) p3 = atomicAdd(&g_cur[r][d.w], 1);
            if (p0 >= 0) g_csr[r][p0] = s.x;
            if (p1 >= 0) g_csr[r][p1] = s.y;
            if (p2 >= 0) g_csr[r][p2] = s.z;
            if (p3 >= 0) g_csr[r][p3] = s.w;
        }
    }
}

__device__ void scan_body(int r) {
    __shared__ __align__(16) int wsum[8];
    __shared__ int carry;
    const int tid = threadIdx.x;
    const int lane = tid & 31;
    const int wid  = tid >> 5;
    if (tid == 0) carry = 0;
    __syncthreads();
    for (int base = 0; base < NN; base += 256) {
        int i = base + tid;
        int v = (i < NN) ? g_deg[r][i] : 0;
        int x = v;
#pragma unroll
        for (int o = 1; o < 32; o <<= 1) {
            int y = __shfl_up_sync(0xffffffffu, x, o);
            if (lane >= o) x += y;
        }
        if (lane == 31) wsum[wid] = x;
        __syncthreads();
        if (tid < 8) {
            int w = wsum[tid];
#pragma unroll
            for (int o = 1; o < 8; o <<= 1) {
                int y = __shfl_up_sync(0x000000ffu, w, o);
                if (tid >= o) w += y;
            }
            wsum[tid] = w;
        }
        __syncthreads();
        int excl = x - v + (wid > 0 ? wsum[wid - 1] : 0) + carry;
        if (i < NN) { g_off[r][i] = excl; g_cur[r][i] = excl; }
        int total = wsum[7];
        __syncthreads();
        if (tid == 0) carry += total;
        __syncthreads();
    }
    if (tid == 0) {
        g_off[r][NN] = carry;
        __threadfence();
        atomicAdd(&g_scan_done, 1);
    }
}

// ---------------- kernels -------------------------------------------------------
#define EMB_TILES 782   /* ceil(50000/64) */
#define HREL_TILES 782  /* ceil(50000/64), BM=64 half GEMM */
#define FIN_TILES 391   /* ceil(50000/128) */
#define CNT_BLKS  128
#define FILL_BLKS 592
#define K3_GEMM   (NREL * HREL_TILES)   /* 2346 */

__global__ void zero_deg_kernel() {
    int i = blockIdx.x * blockDim.x + threadIdx.x;
    if (i == 0) g_scan_done = 0;
    if (i < NREL * NN) ((int*)g_deg)[i] = 0;
}

// K2: degree count (first 128 blocks) + embedder GEMM (fp32)
__global__ __launch_bounds__(256)
void k2_emb_count(const float* __restrict__ x, const float* __restrict__ emb_w,
                  const float* __restrict__ emb_b,
                  const int* __restrict__ ei, int E) {
    if (blockIdx.x < CNT_BLKS)
        count_body(ei, E, blockIdx.x, CNT_BLKS);
    else
        sgemm_body<64, 128, 20, 4, 8, 0>(x, emb_w, emb_b, nullptr, NN, 300,
                                         blockIdx.x - CNT_BLKS);
}

// K3: scan (blocks 0-2) + layer-0 relation GEMMs (half2) + flag-gated CSR fill
__global__ __launch_bounds__(256)
void k3_rel_scan_fill(const float* __restrict__ w,
                      const int* __restrict__ ei, int E) {
    int b = blockIdx.x;
    if (b < NREL) {
        scan_body(b);
    } else if (b < NREL + K3_GEMM) {
        b -= NREL;
        hgemm_body(w, b / HREL_TILES, b % HREL_TILES);
    } else {
        if (threadIdx.x == 0)
            while (atomicAdd(&g_scan_done, 0) < NREL) { }
        __syncthreads();
        fill_body(ei, E, b - NREL - K3_GEMM, FILL_BLKS);
    }
}

// layer-1 relation GEMMs (half2)
__global__ __launch_bounds__(256)
void rel_gemm_kernel(const float* __restrict__ w) {
    hgemm_body(w, blockIdx.y, blockIdx.x);
}

// final linear (fp32)
__global__ __launch_bounds__(256)
void fin_gemm_kernel(const float* __restrict__ w, const float* __restrict__ b,
                     float* __restrict__ out) {
    sgemm_body<128, 64, 16, 8, 4, 2>(nullptr, w, b, out, NN, HID, blockIdx.x);
}

// ---------------- CSR gather: warp per node, HADD2 chunk accumulation ---------
__launch_bounds__(256)
__global__ void gather_kernel(const float* __restrict__ bias) {
    const int node = (blockIdx.x * blockDim.x + threadIdx.x) >> 5;
    const int lane = threadIdx.x & 31;
    if (node >= NN) return;
    const int c0 = lane * 4;

    float4 tot;
    tot.x = bias[c0 + 0] + bias[HID + c0 + 0] + bias[2 * HID + c0 + 0];
    tot.y = bias[c0 + 1] + bias[HID + c0 + 1] + bias[2 * HID + c0 + 1];
    tot.z = bias[c0 + 2] + bias[HID + c0 + 2] + bias[2 * HID + c0 + 2];
    tot.w = bias[c0 + 3] + bias[HID + c0 + 3] + bias[2 * HID + c0 + 3];

    const __half2 hz = __floats2half2_rn(0.f, 0.f);
#pragma unroll
    for (int r = 0; r < NREL; r++) {
        const __half* hwr = g_hw[r];
        float4 a;
        {   // self loop (pre-scaled), straight to fp32
            uint2 raw = *(const uint2*)&hwr[(size_t)node * HID + c0];
            float2 f01 = __half22float2(*(__half2*)&raw.x);
            float2 f23 = __half22float2(*(__half2*)&raw.y);
            a.x = f01.x; a.y = f01.y; a.z = f23.x; a.w = f23.y;
        }
        const int beg = g_off[r][node];
        const int end = g_off[r][node + 1];
        const int* __restrict__ csr = g_csr[r];
        for (int t = beg; t < end; t += 32) {
            int idx = (t + lane < end) ? csr[t + lane] : 0;
            int n = end - t; if (n > 32) n = 32;
            __half2 ah0 = hz, ah1 = hz;     // fp16 accum within <=32-edge chunk
            for (int j = 0; j < n; j++) {
                int s = __shfl_sync(0xffffffffu, idx, j);
                uint2 raw = *(const uint2*)&hwr[(size_t)s * HID + c0];
                ah0 = __hadd2(ah0, *(__half2*)&raw.x);
                ah1 = __hadd2(ah1, *(__half2*)&raw.y);
            }
            float2 f01 = __half22float2(ah0);
            float2 f23 = __half22float2(ah1);
            a.x += f01.x; a.y += f01.y; a.z += f23.x; a.w += f23.y;
        }
        float dd = rsqrtf((float)g_deg[r][node] + 1.0f);
        tot.x += a.x * dd; tot.y += a.y * dd;
        tot.z += a.z * dd; tot.w += a.w * dd;
    }
    tot.x = fmaxf(tot.x, 0.f);
    tot.y = fmaxf(tot.y, 0.f);
    tot.z = fmaxf(tot.z, 0.f);
    tot.w = fmaxf(tot.w, 0.f);
    ((float4*)g_h)[(size_t)node * (HID / 4) + lane] = tot;
}

// ---------------- launch ------------------------------------------------------
extern "C" void kernel_launch(void* const* d_in, const int* in_sizes, int n_in,
                              void* d_out, int out_size) {
    const float* x     = (const float*)d_in[0];
    const int*   ei    = (const int*)d_in[1];   // int32 (JAX x64 disabled)
    const float* emb_w = (const float*)d_in[2];
    const float* emb_b = (const float*)d_in[3];
    const float* w0    = (const float*)d_in[4];
    const float* b0    = (const float*)d_in[5];
    const float* w1    = (const float*)d_in[6];
    const float* b1    = (const float*)d_in[7];
    const float* lin_w = (const float*)d_in[8];
    const float* lin_b = (const float*)d_in[9];
    float* out = (float*)d_out;

    const int E = in_sizes[1] / (2 * NREL);
    const int gather_blocks = (NN * 32 + 255) / 256;   // warp per node

    // stage 1: zero degree counters + scan flag
    zero_deg_kernel<<<(NREL * NN + 255) / 256, 256>>>();

    // stage 2: degree count || embedder GEMM
    k2_emb_count<<<CNT_BLKS + EMB_TILES, 256>>>(x, emb_w, emb_b, ei, E);

    // stage 3: scan || layer-0 relation GEMMs (HFMA2) || CSR fill (gated tail)
    k3_rel_scan_fill<<<NREL + K3_GEMM + FILL_BLKS, 256>>>(w0, ei, E);

    // layer-0 aggregate
    gather_kernel<<<gather_blocks, 256>>>(b0);

    // layer 1
    rel_gemm_kernel<<<dim3(HREL_TILES, NREL), 256>>>(w1);
    gather_kernel<<<gather_blocks, 256>>>(b1);

    // final linear
    fin_gemm_kernel<<<FIN_TILES, 256>>>(lin_w, lin_b, out);
}